// round 1
// baseline (speedup 1.0000x reference)
#include <cuda_runtime.h>
#include <stdint.h>

#define ATT     1024
#define GM1     14          // groups actually written (G-1)
#define LP1     16          // rows per class
#define GSIZE   64
#define NCLASS  6000
#define NUNSEEN 1200
#define NSEEN   4800

// Persistent scratch (allocation-free per harness rules)
__device__ uint32_t g_colmask[ATT];          // bit l set => column in group l-2
__device__ float    g_beta[LP1];             // g_beta[l] = beta[l-2] (l>=2), else 0
__device__ float    g_cntbeta2[GM1];         // distinct_count_g * beta_g^2
__device__ float    g_inv[NCLASS * LP1];     // 1 / max(||row||, 1e-12)

// ---------------------------------------------------------------------------
// Kernel 1: build column membership masks + distinct counts. One block.
// ---------------------------------------------------------------------------
__global__ void k_mask(const int* __restrict__ group_cols,
                       const float* __restrict__ betas) {
    __shared__ uint32_t s_mask[ATT];
    __shared__ int s_cnt[GM1];
    int t = threadIdx.x;
    s_mask[t] = 0u;
    if (t < GM1) s_cnt[t] = 0;
    __syncthreads();
    if (t < GM1 * GSIZE) {
        int g   = t / GSIZE;
        int col = group_cols[t];
        atomicOr(&s_mask[col], 1u << (g + 2));
    }
    __syncthreads();
    uint32_t m = s_mask[t];
    g_colmask[t] = m;
#pragma unroll
    for (int g = 0; g < GM1; ++g)
        if (m & (1u << (g + 2))) atomicAdd(&s_cnt[g], 1);
    __syncthreads();
    if (t < GM1) {
        float b = betas[t];
        g_beta[t + 2]  = b;
        g_cntbeta2[t]  = (float)s_cnt[t] * b * b;
    }
    if (t < 2) g_beta[t] = 0.f;
}

// ---------------------------------------------------------------------------
// Kernel 2: per-class inverse norms for all 16 layers. One block per class.
//   norm^2(l<2)  = sum(attr^2)
//   norm^2(l>=2) = sum(attr^2) - sum_masked(attr^2) + cnt*beta^2
// ---------------------------------------------------------------------------
__global__ void __launch_bounds__(256) k_norm(const float* __restrict__ attr) {
    const int c = blockIdx.x;
    const int t = threadIdx.x;
    const float* row = attr + (size_t)c * ATT;

    float tot = 0.f;
    float gs[GM1];
#pragma unroll
    for (int g = 0; g < GM1; ++g) gs[g] = 0.f;

#pragma unroll
    for (int it = 0; it < 4; ++it) {
        int a = t + it * 256;
        float v  = row[a];
        float v2 = v * v;
        tot += v2;
        uint32_t m = g_colmask[a];
#pragma unroll
        for (int g = 0; g < GM1; ++g)
            if (m & (1u << (g + 2))) gs[g] += v2;
    }

    // warp reduce all 15 sums
#pragma unroll
    for (int o = 16; o; o >>= 1) {
        tot += __shfl_xor_sync(0xffffffffu, tot, o);
#pragma unroll
        for (int g = 0; g < GM1; ++g)
            gs[g] += __shfl_xor_sync(0xffffffffu, gs[g], o);
    }

    __shared__ float s_red[8][15];
    int w = t >> 5, lane = t & 31;
    if (lane == 0) {
        s_red[w][0] = tot;
#pragma unroll
        for (int g = 0; g < GM1; ++g) s_red[w][g + 1] = gs[g];
    }
    __syncthreads();

    if (t < LP1) {
        float tt = 0.f;
#pragma unroll
        for (int w2 = 0; w2 < 8; ++w2) tt += s_red[w2][0];
        float x;
        if (t < 2) {
            x = tt;
        } else {
            float gsum = 0.f;
#pragma unroll
            for (int w2 = 0; w2 < 8; ++w2) gsum += s_red[w2][t - 1]; // gs[t-2]
            x = tt - gsum + g_cntbeta2[t - 2];
        }
        float nrm = sqrtf(x);
        g_inv[c * LP1 + t] = 1.0f / fmaxf(nrm, 1e-12f);
    }
}

// ---------------------------------------------------------------------------
// Kernel 3: transposed output writer.
//   out[a * (nclass*16) + i*16 + l] = val(cls(i), l, a)
// Tile: 16 class-slots x 32 attr-dims per block; 256 threads.
// Warp store pattern: 32 consecutive float4 = 512B contiguous per STG wave.
// ---------------------------------------------------------------------------
__global__ void __launch_bounds__(256) k_write(
    const float* __restrict__ attr,
    const int*   __restrict__ map,     // nullptr => identity
    int nclass,
    float* __restrict__ out)
{
    const int stride = nclass * LP1;
    const int c0 = blockIdx.x * 16;
    const int a0 = blockIdx.y * 32;

    __shared__ float    s_attr[16][33];  // [class][a] padded
    __shared__ float    s_inv [16][17];  // [class][l]
    __shared__ int      s_cls [16];
    __shared__ uint32_t s_cm  [32];
    __shared__ float    s_beta[LP1];

    const int t = threadIdx.x;
    if (t < 16)                s_cls[t]       = map ? map[c0 + t] : (c0 + t);
    if (t >= 32 && t < 64)     s_cm[t - 32]   = g_colmask[a0 + (t - 32)];
    if (t >= 64 && t < 80)     s_beta[t - 64] = g_beta[t - 64];
    __syncthreads();

    if (t < 128) {                       // attr tile: 16 x 32 floats
        int ci = t >> 3, j = t & 7;
        float4 v = *(const float4*)(attr + (size_t)s_cls[ci] * ATT + a0 + j * 4);
        s_attr[ci][j * 4 + 0] = v.x; s_attr[ci][j * 4 + 1] = v.y;
        s_attr[ci][j * 4 + 2] = v.z; s_attr[ci][j * 4 + 3] = v.w;
    } else if (t < 192) {                // inv tile: 16 x 16 floats
        int t2 = t - 128;
        int ci = t2 >> 2, q = t2 & 3;
        float4 v = *(const float4*)(g_inv + (size_t)s_cls[ci] * LP1 + q * 4);
        s_inv[ci][q * 4 + 0] = v.x; s_inv[ci][q * 4 + 1] = v.y;
        s_inv[ci][q * 4 + 2] = v.z; s_inv[ci][q * 4 + 3] = v.w;
    }
    __syncthreads();

    const int q    = t & 3;          // layer quad (l = 4q..4q+3)
    const int ci   = (t >> 2) & 15;  // class within tile
    const int asub = t >> 6;         // a sub-row 0..3

    const float inv0 = s_inv[ci][4 * q + 0], inv1 = s_inv[ci][4 * q + 1];
    const float inv2 = s_inv[ci][4 * q + 2], inv3 = s_inv[ci][4 * q + 3];
    const float bv0 = s_beta[4 * q + 0] * inv0, bv1 = s_beta[4 * q + 1] * inv1;
    const float bv2 = s_beta[4 * q + 2] * inv2, bv3 = s_beta[4 * q + 3] * inv3;

    float* obase = out + (size_t)(c0 + ci) * LP1 + 4 * q;

#pragma unroll
    for (int it = 0; it < 8; ++it) {
        int aa = it * 4 + asub;
        uint32_t m = s_cm[aa] >> (4 * q);
        float av = s_attr[ci][aa];
        float4 v;
        v.x = (m & 1u) ? bv0 : av * inv0;
        v.y = (m & 2u) ? bv1 : av * inv1;
        v.z = (m & 4u) ? bv2 : av * inv2;
        v.w = (m & 8u) ? bv3 : av * inv3;
        *(float4*)(obase + (size_t)(a0 + aa) * stride) = v;
    }
}

// ---------------------------------------------------------------------------
extern "C" void kernel_launch(void* const* d_in, const int* in_sizes, int n_in,
                              void* d_out, int out_size) {
    const float* attribute  = (const float*)d_in[0];
    const float* betas      = (const float*)d_in[1];
    const int*   group_cols = (const int*)d_in[2];
    const int*   unseen     = (const int*)d_in[3];
    const int*   seen       = (const int*)d_in[4];
    float* out = (float*)d_out;

    k_mask<<<1, ATT>>>(group_cols, betas);
    k_norm<<<NCLASS, 256>>>(attribute);

    float* out_zsl  = out;
    float* out_seen = out_zsl  + (size_t)ATT * NUNSEEN * LP1;
    float* out_gzsl = out_seen + (size_t)ATT * NSEEN   * LP1;

    k_write<<<dim3(NUNSEEN / 16, ATT / 32), 256>>>(attribute, unseen,  NUNSEEN, out_zsl);
    k_write<<<dim3(NSEEN   / 16, ATT / 32), 256>>>(attribute, seen,    NSEEN,   out_seen);
    k_write<<<dim3(NCLASS  / 16, ATT / 32), 256>>>(attribute, nullptr, NCLASS,  out_gzsl);
}

// round 2
// speedup vs baseline: 1.1169x; 1.1169x over previous
#include <cuda_runtime.h>
#include <stdint.h>

#define ATT     1024
#define GM1     14          // groups actually written (G-1)
#define LP1     16          // rows per class
#define GSIZE   64
#define NCLASS  6000
#define NUNSEEN 1200
#define NSEEN   4800

// Segment block counts (16-class x 32-attr tiles)
#define BLK_ZSL   ((NUNSEEN / 16) * (ATT / 32))   // 2400
#define BLK_SEEN  ((NSEEN   / 16) * (ATT / 32))   // 9600
#define BLK_GZSL  ((NCLASS  / 16) * (ATT / 32))   // 12000
#define BLK_TOTAL (BLK_ZSL + BLK_SEEN + BLK_GZSL) // 24000

// Persistent scratch (allocation-free per harness rules)
__device__ uint32_t g_colmask[ATT];          // bit l set => column in group l-2
__device__ float    g_beta[LP1];             // g_beta[l] = beta[l-2] (l>=2), else 0
__device__ float    g_cntbeta2[GM1];         // distinct_count_g * beta_g^2
__device__ float    g_inv[NCLASS * LP1];     // 1 / max(||row||, 1e-12)

// ---------------------------------------------------------------------------
// Kernel 1: build column membership masks + distinct counts. One block.
// ---------------------------------------------------------------------------
__global__ void k_mask(const int* __restrict__ group_cols,
                       const float* __restrict__ betas) {
    __shared__ uint32_t s_mask[ATT];
    __shared__ int s_cnt[GM1];
    int t = threadIdx.x;
    s_mask[t] = 0u;
    if (t < GM1) s_cnt[t] = 0;
    __syncthreads();
    if (t < GM1 * GSIZE) {
        int g   = t / GSIZE;
        int col = group_cols[t];
        atomicOr(&s_mask[col], 1u << (g + 2));
    }
    __syncthreads();
    uint32_t m = s_mask[t];
    g_colmask[t] = m;
#pragma unroll
    for (int g = 0; g < GM1; ++g)
        if (m & (1u << (g + 2))) atomicAdd(&s_cnt[g], 1);
    __syncthreads();
    if (t < GM1) {
        float b = betas[t];
        g_beta[t + 2]  = b;
        g_cntbeta2[t]  = (float)s_cnt[t] * b * b;
    }
    if (t < 2) g_beta[t] = 0.f;
}

// ---------------------------------------------------------------------------
// Kernel 2: per-class inverse norms for all 16 layers. One block per class.
// ---------------------------------------------------------------------------
__global__ void __launch_bounds__(256) k_norm(const float* __restrict__ attr) {
    const int c = blockIdx.x;
    const int t = threadIdx.x;
    const float* row = attr + (size_t)c * ATT;

    float tot = 0.f;
    float gs[GM1];
#pragma unroll
    for (int g = 0; g < GM1; ++g) gs[g] = 0.f;

#pragma unroll
    for (int it = 0; it < 4; ++it) {
        int a = t + it * 256;
        float v  = __ldca(row + a);
        float v2 = v * v;
        tot += v2;
        uint32_t m = g_colmask[a];
#pragma unroll
        for (int g = 0; g < GM1; ++g)
            if (m & (1u << (g + 2))) gs[g] += v2;
    }

#pragma unroll
    for (int o = 16; o; o >>= 1) {
        tot += __shfl_xor_sync(0xffffffffu, tot, o);
#pragma unroll
        for (int g = 0; g < GM1; ++g)
            gs[g] += __shfl_xor_sync(0xffffffffu, gs[g], o);
    }

    __shared__ float s_red[8][15];
    int w = t >> 5, lane = t & 31;
    if (lane == 0) {
        s_red[w][0] = tot;
#pragma unroll
        for (int g = 0; g < GM1; ++g) s_red[w][g + 1] = gs[g];
    }
    __syncthreads();

    if (t < LP1) {
        float tt = 0.f;
#pragma unroll
        for (int w2 = 0; w2 < 8; ++w2) tt += s_red[w2][0];
        float x;
        if (t < 2) {
            x = tt;
        } else {
            float gsum = 0.f;
#pragma unroll
            for (int w2 = 0; w2 < 8; ++w2) gsum += s_red[w2][t - 1]; // gs[t-2]
            x = tt - gsum + g_cntbeta2[t - 2];
        }
        float nrm = sqrtf(x);
        g_inv[c * LP1 + t] = 1.0f / fmaxf(nrm, 1e-12f);
    }
}

// ---------------------------------------------------------------------------
// Kernel 3: fused transposed writer for all three output segments.
// Block id decodes segment -> (map, nclass, out base). Tile: 16 classes x
// 32 attrs, 256 threads; each warp wave emits 512B contiguous float4
// streaming stores (__stcs, evict-first: output has zero reuse).
// ---------------------------------------------------------------------------
__global__ void __launch_bounds__(256) k_write_fused(
    const float* __restrict__ attr,
    const int*   __restrict__ unseen,
    const int*   __restrict__ seen,
    float* __restrict__ out)
{
    int b = blockIdx.x;
    const int* map;
    int nclass;
    float* obaseseg;

    // Largest segment first (gzsl), then seen, then zsl.
    if (b < BLK_GZSL) {
        map = nullptr; nclass = NCLASS;
        obaseseg = out + (size_t)ATT * (NUNSEEN + NSEEN) * LP1;
    } else if (b < BLK_GZSL + BLK_SEEN) {
        b -= BLK_GZSL;
        map = seen; nclass = NSEEN;
        obaseseg = out + (size_t)ATT * NUNSEEN * LP1;
    } else {
        b -= BLK_GZSL + BLK_SEEN;
        map = unseen; nclass = NUNSEEN;
        obaseseg = out;
    }

    const int c_tiles = nclass >> 4;
    const int c0 = (b % c_tiles) * 16;
    const int a0 = (b / c_tiles) * 32;
    const int stride = nclass * LP1;

    __shared__ float    s_attr[16][33];
    __shared__ float    s_inv [16][17];
    __shared__ int      s_cls [16];
    __shared__ uint32_t s_cm  [32];
    __shared__ float    s_beta[LP1];

    const int t = threadIdx.x;
    if (t < 16)                s_cls[t]       = map ? map[c0 + t] : (c0 + t);
    if (t >= 32 && t < 64)     s_cm[t - 32]   = g_colmask[a0 + (t - 32)];
    if (t >= 64 && t < 80)     s_beta[t - 64] = g_beta[t - 64];
    __syncthreads();

    if (t < 128) {                       // attr tile: 16 x 32 floats
        int ci = t >> 3, j = t & 7;
        float4 v = __ldg((const float4*)(attr + (size_t)s_cls[ci] * ATT + a0 + j * 4));
        s_attr[ci][j * 4 + 0] = v.x; s_attr[ci][j * 4 + 1] = v.y;
        s_attr[ci][j * 4 + 2] = v.z; s_attr[ci][j * 4 + 3] = v.w;
    } else if (t < 192) {                // inv tile: 16 x 16 floats
        int t2 = t - 128;
        int ci = t2 >> 2, q = t2 & 3;
        float4 v = *(const float4*)(g_inv + (size_t)s_cls[ci] * LP1 + q * 4);
        s_inv[ci][q * 4 + 0] = v.x; s_inv[ci][q * 4 + 1] = v.y;
        s_inv[ci][q * 4 + 2] = v.z; s_inv[ci][q * 4 + 3] = v.w;
    }
    __syncthreads();

    const int q    = t & 3;          // layer quad (l = 4q..4q+3)
    const int ci   = (t >> 2) & 15;  // class within tile
    const int asub = t >> 6;         // a sub-row 0..3

    const float inv0 = s_inv[ci][4 * q + 0], inv1 = s_inv[ci][4 * q + 1];
    const float inv2 = s_inv[ci][4 * q + 2], inv3 = s_inv[ci][4 * q + 3];
    const float bv0 = s_beta[4 * q + 0] * inv0, bv1 = s_beta[4 * q + 1] * inv1;
    const float bv2 = s_beta[4 * q + 2] * inv2, bv3 = s_beta[4 * q + 3] * inv3;

    float* obase = obaseseg + (size_t)(c0 + ci) * LP1 + 4 * q;

#pragma unroll
    for (int it = 0; it < 8; ++it) {
        int aa = it * 4 + asub;
        uint32_t m = s_cm[aa] >> (4 * q);
        float av = s_attr[ci][aa];
        float4 v;
        v.x = (m & 1u) ? bv0 : av * inv0;
        v.y = (m & 2u) ? bv1 : av * inv1;
        v.z = (m & 4u) ? bv2 : av * inv2;
        v.w = (m & 8u) ? bv3 : av * inv3;
        __stcs((float4*)(obase + (size_t)(a0 + aa) * stride), v);
    }
}

// ---------------------------------------------------------------------------
extern "C" void kernel_launch(void* const* d_in, const int* in_sizes, int n_in,
                              void* d_out, int out_size) {
    const float* attribute  = (const float*)d_in[0];
    const float* betas      = (const float*)d_in[1];
    const int*   group_cols = (const int*)d_in[2];
    const int*   unseen     = (const int*)d_in[3];
    const int*   seen       = (const int*)d_in[4];
    float* out = (float*)d_out;

    k_mask<<<1, ATT>>>(group_cols, betas);
    k_norm<<<NCLASS, 256>>>(attribute);
    k_write_fused<<<BLK_TOTAL, 256>>>(attribute, unseen, seen, out);
}

// round 4
// speedup vs baseline: 1.1223x; 1.0049x over previous
#include <cuda_runtime.h>
#include <stdint.h>

#define ATT     1024
#define GM1     14          // groups actually written (G-1)
#define LP1     16          // rows per class
#define GSIZE   64
#define NCLASS  6000
#define NUNSEEN 1200
#define NSEEN   4800
#define CPB     8           // classes per block

#define BLK_GZSL (NCLASS  / CPB)   // 750
#define BLK_SEEN (NSEEN   / CPB)   // 600
#define BLK_ZSL  (NUNSEEN / CPB)   // 150
#define BLK_TOTAL (BLK_GZSL + BLK_SEEN + BLK_ZSL)  // 1500

// ---------------------------------------------------------------------------
// Single fused kernel: per block, stage 8 attribute rows in smem, rebuild the
// column-group mask locally (tiny, L2-resident), compute the 8x16 inverse
// norms in-block, then stream the transposed normalized tile to the output.
// ---------------------------------------------------------------------------
__global__ void __launch_bounds__(256) k_all(
    const float* __restrict__ attr,
    const float* __restrict__ betas,
    const int*   __restrict__ group_cols,
    const int*   __restrict__ unseen,
    const int*   __restrict__ seen,
    float* __restrict__ out)
{
    // ---- segment decode (largest segment first for wave balance) ----
    int b = blockIdx.x;
    const int* map;
    int nclass;
    float* obaseseg;
    if (b < BLK_GZSL) {
        map = nullptr; nclass = NCLASS;
        obaseseg = out + (size_t)ATT * (NUNSEEN + NSEEN) * LP1;
    } else if (b < BLK_GZSL + BLK_SEEN) {
        b -= BLK_GZSL;
        map = seen; nclass = NSEEN;
        obaseseg = out + (size_t)ATT * NUNSEEN * LP1;
    } else {
        b -= BLK_GZSL + BLK_SEEN;
        map = unseen; nclass = NUNSEEN;
        obaseseg = out;
    }
    const int c0 = b * CPB;
    const int stride = nclass * LP1;

    __shared__ float    s_attr[CPB][ATT + 1];   // 32.8 KB
    __shared__ uint32_t s_mask[ATT];            // 4 KB
    __shared__ float    s_inv [CPB][LP1];
    __shared__ float    s_red [CPB][15];
    __shared__ int      s_cnt [GM1];
    __shared__ float    s_cb2 [GM1];
    __shared__ float    s_beta[LP1];
    __shared__ int      s_cls [CPB];

    const int t    = threadIdx.x;
    const int w    = t >> 5;
    const int lane = t & 31;

    // ---- init ----
#pragma unroll
    for (int i = 0; i < 4; ++i) s_mask[i * 256 + t] = 0u;
    if (t < GM1)  s_cnt[t] = 0;
    if (t < CPB)  s_cls[t] = map ? __ldg(map + c0 + t) : (c0 + t);
    if (t < GM1)  s_beta[t + 2] = __ldg(betas + t);
    if (t < 2)    s_beta[t] = 0.f;
    __syncthreads();

    // ---- column mask (strided: 896 entries, 256 threads) + attr tile load ----
    for (int i = t; i < GM1 * GSIZE; i += 256) {
        int col = __ldg(group_cols + i);
        atomicOr(&s_mask[col], 1u << ((i >> 6) + 2));
    }
#pragma unroll
    for (int i = 0; i < 8; ++i) {
        int idx = i * 256 + t;            // 0..2047 float4 slots
        int ci  = idx >> 8;               // class 0..7
        int j   = idx & 255;              // float4 within row
        float4 v = __ldg((const float4*)(attr + (size_t)s_cls[ci] * ATT) + j);
        s_attr[ci][j * 4 + 0] = v.x; s_attr[ci][j * 4 + 1] = v.y;
        s_attr[ci][j * 4 + 2] = v.z; s_attr[ci][j * 4 + 3] = v.w;
    }
    __syncthreads();

    // ---- distinct-count per group via ballots ----
#pragma unroll
    for (int i = 0; i < 4; ++i) {
        uint32_t m = s_mask[i * 256 + t];
#pragma unroll
        for (int g = 0; g < GM1; ++g) {
            uint32_t bal = __ballot_sync(0xffffffffu, m & (1u << (g + 2)));
            if (lane == 0 && bal) atomicAdd(&s_cnt[g], __popc(bal));
        }
    }
    __syncthreads();
    if (t < GM1) s_cb2[t] = (float)s_cnt[t] * s_beta[t + 2] * s_beta[t + 2];
    __syncthreads();

    // ---- per-class inverse norms: warp w handles class w ----
    {
        float tot = 0.f;
        float gs[GM1];
#pragma unroll
        for (int g = 0; g < GM1; ++g) gs[g] = 0.f;
#pragma unroll
        for (int j = 0; j < 32; ++j) {
            int a = j * 32 + lane;
            float v  = s_attr[w][a];
            float v2 = v * v;
            tot += v2;
            uint32_t m = s_mask[a];
#pragma unroll
            for (int g = 0; g < GM1; ++g)
                if (m & (1u << (g + 2))) gs[g] += v2;
        }
#pragma unroll
        for (int o = 16; o; o >>= 1) {
            tot += __shfl_xor_sync(0xffffffffu, tot, o);
#pragma unroll
            for (int g = 0; g < GM1; ++g)
                gs[g] += __shfl_xor_sync(0xffffffffu, gs[g], o);
        }
        if (lane == 0) {
            s_red[w][0] = tot;
#pragma unroll
            for (int g = 0; g < GM1; ++g) s_red[w][g + 1] = gs[g];
        }
        __syncwarp();
        if (lane < LP1) {
            float tt = s_red[w][0];
            float x  = (lane < 2) ? tt
                                  : tt - s_red[w][lane - 1] + s_cb2[lane - 2];
            s_inv[w][lane] = 1.0f / fmaxf(sqrtf(x), 1e-12f);
        }
    }
    __syncthreads();

    // ---- streaming transposed write ----
    // warp w, iteration i -> attr row a = i*8 + w; lane -> (ci, q):
    // warp stores 32 float4 = 512B contiguous: out[a*stride + (c0..c0+7)*16 + 0..15]
    const int ci = lane >> 2;
    const int q  = lane & 3;

    const float inv0 = s_inv[ci][4 * q + 0], inv1 = s_inv[ci][4 * q + 1];
    const float inv2 = s_inv[ci][4 * q + 2], inv3 = s_inv[ci][4 * q + 3];
    const float bv0 = s_beta[4 * q + 0] * inv0, bv1 = s_beta[4 * q + 1] * inv1;
    const float bv2 = s_beta[4 * q + 2] * inv2, bv3 = s_beta[4 * q + 3] * inv3;

    float* ob = obaseseg + (size_t)(c0 + ci) * LP1 + 4 * q;
    const float* arow = s_attr[ci];

#pragma unroll 4
    for (int i = 0; i < ATT / 8; ++i) {
        int a = i * 8 + w;
        uint32_t m = s_mask[a] >> (4 * q);
        float av = arow[a];
        float4 v;
        v.x = (m & 1u) ? bv0 : av * inv0;
        v.y = (m & 2u) ? bv1 : av * inv1;
        v.z = (m & 4u) ? bv2 : av * inv2;
        v.w = (m & 8u) ? bv3 : av * inv3;
        __stcs((float4*)(ob + (size_t)a * stride), v);
    }
}

// ---------------------------------------------------------------------------
extern "C" void kernel_launch(void* const* d_in, const int* in_sizes, int n_in,
                              void* d_out, int out_size) {
    const float* attribute  = (const float*)d_in[0];
    const float* betas      = (const float*)d_in[1];
    const int*   group_cols = (const int*)d_in[2];
    const int*   unseen     = (const int*)d_in[3];
    const int*   seen       = (const int*)d_in[4];
    float* out = (float*)d_out;

    k_all<<<BLK_TOTAL, 256>>>(attribute, betas, group_cols, unseen, seen, out);
}